// round 1
// baseline (speedup 1.0000x reference)
#include <cuda_runtime.h>
#include <math.h>

#define DIM 200
#define RED 8
#define JC 40            // columns per chunk
#define NCH 5            // chunks (5*40 = 200)
#define TSTRIDE 41       // padded smem row stride (gcd(41%32,32)=1 -> conflict free)

// ---- persistent device scratch (no allocations allowed) ----
__device__ float g_kp[2][DIM * RED];   // relu(kernel_p), relu(kernel_n)
__device__ float g_Wc[2 * 128];        // lin2_w @ lin1_w  (2 x 128)
__device__ float g_bc[2];              // lin2_w @ lin1_b + lin2_b

// =====================================================================
// Setup: relu(kernels), fused linear weights, and the data-independent loss
// =====================================================================
__global__ void gnn_setup_kernel(
    const float* __restrict__ kp_p, const float* __restrict__ kp_n,
    const float* __restrict__ Wp1, const float* __restrict__ Wp2, const float* __restrict__ Wp3,
    const float* __restrict__ Wn1, const float* __restrict__ Wn2, const float* __restrict__ Wn3,
    const float* __restrict__ lin1_w, const float* __restrict__ lin1_b,
    const float* __restrict__ lin2_w, const float* __restrict__ lin2_b,
    float* __restrict__ out, int loss_idx, int write_loss)
{
    __shared__ float gram_s[128];
    __shared__ float loss_s;
    int tid = threadIdx.x;           // launched with 256 threads exactly
    if (tid == 0) loss_s = 0.f;
    float lp = 0.f;

    // relu kernels + neg penalty + L1(|relu|) penalty
    for (int i = tid; i < DIM * RED; i += 256) {
        float a = kp_p[i], b = kp_n[i];
        float ra = fmaxf(a, 0.f), rb = fmaxf(b, 0.f);
        g_kp[0][i] = ra;
        g_kp[1][i] = rb;
        lp += 0.1f * fmaxf(1e-6f - a, 0.f) + 0.1f * fmaxf(1e-6f - b, 0.f);
        lp += 0.05f * (ra + rb);
    }
    // gcn neg-penalties on the six 8x8 W's
    if (tid < 64) {
        lp += 0.2f * (fmaxf(1e-6f - Wp1[tid], 0.f) + fmaxf(1e-6f - Wp2[tid], 0.f) +
                      fmaxf(1e-6f - Wp3[tid], 0.f) + fmaxf(1e-6f - Wn1[tid], 0.f) +
                      fmaxf(1e-6f - Wn2[tid], 0.f) + fmaxf(1e-6f - Wn3[tid], 0.f));
    }
    __syncthreads();   // g_kp visible to block

    // gram = kp^T kp, ortho penalty on off-diagonals
    if (tid < 128) {
        int side = tid >> 6, a = (tid >> 3) & 7, b2 = tid & 7;
        const float* kp = g_kp[side];
        float s = 0.f;
        for (int n = 0; n < DIM; n++) s += kp[n * 8 + a] * kp[n * 8 + b2];
        gram_s[tid] = s;
        if (a != b2) lp += 0.2f * s * s;
    }
    __syncthreads();

    // variance of gram diagonal, ddof=1 (0.3 for p-side, 0.5 for n-side)
    if (tid < 2) {
        const float* g = gram_s + tid * 64;
        float mean = 0.f;
        for (int a = 0; a < 8; a++) mean += g[a * 9];
        mean *= 0.125f;
        float v = 0.f;
        for (int a = 0; a < 8; a++) { float d = g[a * 9] - mean; v += d * d; }
        v *= (1.0f / 7.0f);
        lp += (tid ? 0.5f : 0.3f) * v;
    }

    // fused linear:  Wc[c][f] = sum_h lin2_w[c][h] * lin1_w[h][f]
    {
        int c = tid >> 7, f = tid & 127;
        float s = 0.f;
        #pragma unroll
        for (int h = 0; h < 16; h++) s += lin2_w[c * 16 + h] * lin1_w[h * 128 + f];
        g_Wc[tid] = s;
    }
    if (tid < 2) {
        float s = lin2_b[tid];
        #pragma unroll
        for (int h = 0; h < 16; h++) s += lin2_w[tid * 16 + h] * lin1_b[h];
        g_bc[tid] = s;
    }

    atomicAdd(&loss_s, lp);
    __syncthreads();
    if (tid == 0 && write_loss) out[loss_idx] = loss_s;
}

// =====================================================================
// Main: per-batch fused  reduced = kp^T A kp -> 3x GCN -> fused linear
// =====================================================================
__global__ void __launch_bounds__(256, 5) gnn_main_kernel(
    const float* __restrict__ A,
    const float* __restrict__ Wp1, const float* __restrict__ Wp2, const float* __restrict__ Wp3,
    const float* __restrict__ Wn1, const float* __restrict__ Wn2, const float* __restrict__ Wn3,
    float* __restrict__ out)
{
    extern __shared__ float sm[];
    float* tile = sm;                    // DIM*TSTRIDE = 8200
    float* kp_s = tile + DIM * TSTRIDE;  // 1600
    float* W_s  = kp_s + DIM * RED;      // 192 (3 layers x 64)
    float* Rm   = W_s + 192;             // 64
    float* Msm  = Rm + 64;               // 64
    float* Ysm  = Msm + 64;              // 64
    float* Xsm  = Ysm + 64;              // 64
    float* feat = Xsm + 64;              // 128
    float* part = feat + 128;            // 256
    float* AF   = tile;                  // alias: AF (200x8) reuses tile storage

    const int b = blockIdx.x;
    const int tid = threadIdx.x;

    for (int s = 0; s < 2; s++) {
        // stage kp and the three W's for this sign
        for (int i = tid; i < DIM * RED; i += 256) kp_s[i] = g_kp[s][i];
        if (tid < 192) {
            const float* w;
            if (s == 0) w = (tid < 64) ? Wp1 : ((tid < 128) ? Wp2 : Wp3);
            else        w = (tid < 64) ? Wn1 : ((tid < 128) ? Wn2 : Wn3);
            W_s[tid] = w[tid & 63];
        }

        const float4* Ag = (const float4*)(A + ((size_t)b * 2 + s) * (DIM * DIM));
        float af[8];
        #pragma unroll
        for (int m = 0; m < 8; m++) af[m] = 0.f;

        for (int c = 0; c < NCH; c++) {
            __syncthreads();                       // tile reuse barrier
            // ---- stage 200x40 fp32 chunk (float4, 32B-sector aligned) ----
            const int j0q = c * (JC / 4);          // float4 column offset in row
            for (int idx = tid; idx < DIM * (JC / 4); idx += 256) {
                int r  = idx / (JC / 4);
                int c4 = idx - r * (JC / 4);
                float4 v = Ag[r * (DIM / 4) + j0q + c4];
                float* dst = tile + r * TSTRIDE + c4 * 4;
                dst[0] = v.x; dst[1] = v.y; dst[2] = v.z; dst[3] = v.w;
            }
            __syncthreads();
            // ---- AF[n,:] += adj[n, j0:j0+40] @ kp[j0:j0+40, :] ----
            if (tid < DIM) {
                const float* trow = tile + tid * TSTRIDE;
                const float4* kpr = (const float4*)(kp_s + c * JC * RED);
                #pragma unroll
                for (int jj = 0; jj < JC; jj++) {
                    float a  = trow[jj];
                    float4 k0 = kpr[jj * 2];
                    float4 k1 = kpr[jj * 2 + 1];
                    af[0] = fmaf(a, k0.x, af[0]);
                    af[1] = fmaf(a, k0.y, af[1]);
                    af[2] = fmaf(a, k0.z, af[2]);
                    af[3] = fmaf(a, k0.w, af[3]);
                    af[4] = fmaf(a, k1.x, af[4]);
                    af[5] = fmaf(a, k1.y, af[5]);
                    af[6] = fmaf(a, k1.z, af[6]);
                    af[7] = fmaf(a, k1.w, af[7]);
                }
            }
        }
        __syncthreads();                            // tile reads done; alias as AF
        if (tid < DIM) {
            #pragma unroll
            for (int m = 0; m < 8; m++) AF[tid * 8 + m] = af[m];
        }
        __syncthreads();

        // ---- fold: reduced[a,m] = sum_n kp[n,a] * AF[n,m] ----
        {
            int g = tid >> 6, am = tid & 63, a = am >> 3, m = am & 7;
            float sacc = 0.f;
            int n0 = g * 50;
            #pragma unroll 5
            for (int n = n0; n < n0 + 50; n++)
                sacc = fmaf(kp_s[n * 8 + a], AF[n * 8 + m], sacc);
            part[tid] = sacc;
        }
        __syncthreads();
        if (tid < 64) Rm[tid] = part[tid] + part[tid + 64] + part[tid + 128] + part[tid + 192];
        __syncthreads();

        // ---- GCN chain on 8x8 (thread (i,j) per element) ----
        const int i = tid >> 3, j = tid & 7;
        for (int l = 0; l < 3; l++) {
            if (tid < 64) {
                float mv;
                if (l == 0) mv = W_s[tid];                   // x=None -> M = W
                else {
                    mv = 0.f;
                    #pragma unroll
                    for (int k = 0; k < 8; k++)
                        mv = fmaf(Xsm[i * 8 + k], W_s[l * 64 + k * 8 + j], mv);
                }
                Msm[tid] = mv;
            }
            __syncthreads();
            if (tid < 64) {
                float t = 0.f;
                #pragma unroll
                for (int k = 0; k < 8; k++)
                    t = fmaf(Rm[i * 8 + k], Msm[k * 8 + j], t);
                float y = ((i == j) ? 1.0f : 0.0f) + 0.85f * t;
                Ysm[tid] = fmaxf(y, 0.f);
            }
            __syncthreads();
            if (tid < 64) {
                float cs = 0.f;
                #pragma unroll
                for (int r = 0; r < 8; r++) cs += Ysm[r * 8 + j];
                float cm = cs * 0.125f + 1e-6f;
                float z = Ysm[tid] / cm;                     // z >= 0
                Xsm[tid] = z + log1pf(__expf(-z));           // softplus, stable
            }
            __syncthreads();
        }
        if (tid < 64) feat[i * 16 + s * 8 + j] = Xsm[tid];   // concat layout (B,8,16)
        __syncthreads();
    }

    // ---- fused 128 -> 2 linear ----
    if (tid < 2) {
        float acc = g_bc[tid];
        const float* w = g_Wc + tid * 128;
        #pragma unroll 8
        for (int f = 0; f < 128; f++) acc = fmaf(w[f], feat[f], acc);
        out[(size_t)b * 2 + tid] = acc;
    }
}

// =====================================================================
extern "C" void kernel_launch(void* const* d_in, const int* in_sizes, int n_in,
                              void* d_out, int out_size)
{
    const float* A        = (const float*)d_in[0];
    const float* kernel_p = (const float*)d_in[1];
    const float* kernel_n = (const float*)d_in[2];
    const float* Wp1      = (const float*)d_in[3];
    const float* Wp2      = (const float*)d_in[4];
    const float* Wp3      = (const float*)d_in[5];
    const float* Wn1      = (const float*)d_in[6];
    const float* Wn2      = (const float*)d_in[7];
    const float* Wn3      = (const float*)d_in[8];
    const float* lin1_w   = (const float*)d_in[9];
    const float* lin1_b   = (const float*)d_in[10];
    const float* lin2_w   = (const float*)d_in[11];
    const float* lin2_b   = (const float*)d_in[12];
    float* out = (float*)d_out;

    const int B = in_sizes[0] / (2 * DIM * DIM);   // 4096
    const int loss_idx = B * 2;
    const int write_loss = (out_size > loss_idx) ? 1 : 0;

    gnn_setup_kernel<<<1, 256>>>(kernel_p, kernel_n, Wp1, Wp2, Wp3, Wn1, Wn2, Wn3,
                                 lin1_w, lin1_b, lin2_w, lin2_b,
                                 out, loss_idx, write_loss);

    const int smem_floats = DIM * TSTRIDE + DIM * RED + 192 + 64 + 64 + 64 + 64 + 128 + 256;
    gnn_main_kernel<<<B, 256, smem_floats * sizeof(float)>>>(
        A, Wp1, Wp2, Wp3, Wn1, Wn2, Wn3, out);
}

// round 2
// speedup vs baseline: 1.6441x; 1.6441x over previous
#include <cuda_runtime.h>
#include <math.h>

#define DIM 200
#define RED 8
#define JC 20            // columns per chunk
#define NCH 10           // chunks (10*20 = 200)
#define TSTRIDE 20       // smem row stride in floats (80B rows, 16B aligned,
                         // LDS.128 quarter-warp banks 20t mod 32 all distinct)
#define TILEF (DIM * TSTRIDE)   // floats per tile buffer (4000)

// ---- persistent device scratch (no allocations allowed) ----
__device__ float g_kp[2][DIM * RED];   // relu(kernel_p), relu(kernel_n)
__device__ float g_Wc[2 * 128];        // lin2_w @ lin1_w  (2 x 128)
__device__ float g_bc[2];              // lin2_w @ lin1_b + lin2_b

// kp in constant memory: uniform-per-warp access -> LDC/LDCU, zero L1tex traffic
__constant__ float4 c_kp4[2][DIM * 2];  // [sign][j*2 + {0,1}] = kp[j][0..3],[4..7]

// ---------------- cp.async helpers ----------------
__device__ __forceinline__ void cp_async16(void* smem_dst, const void* gmem_src) {
    unsigned saddr = (unsigned)__cvta_generic_to_shared(smem_dst);
    asm volatile("cp.async.cg.shared.global [%0], [%1], 16;\n"
                 :: "r"(saddr), "l"(gmem_src) : "memory");
}
__device__ __forceinline__ void cp_commit() {
    asm volatile("cp.async.commit_group;\n" ::: "memory");
}
template <int N>
__device__ __forceinline__ void cp_wait() {
    asm volatile("cp.async.wait_group %0;\n" :: "n"(N) : "memory");
}

// =====================================================================
// Setup: relu(kernels), fused linear weights, and the data-independent loss
// =====================================================================
__global__ void gnn_setup_kernel(
    const float* __restrict__ kp_p, const float* __restrict__ kp_n,
    const float* __restrict__ Wp1, const float* __restrict__ Wp2, const float* __restrict__ Wp3,
    const float* __restrict__ Wn1, const float* __restrict__ Wn2, const float* __restrict__ Wn3,
    const float* __restrict__ lin1_w, const float* __restrict__ lin1_b,
    const float* __restrict__ lin2_w, const float* __restrict__ lin2_b,
    float* __restrict__ out, int loss_idx, int write_loss)
{
    __shared__ float gram_s[128];
    __shared__ float loss_s;
    int tid = threadIdx.x;           // launched with 256 threads exactly
    if (tid == 0) loss_s = 0.f;
    float lp = 0.f;

    // relu kernels + neg penalty + L1(|relu|) penalty
    for (int i = tid; i < DIM * RED; i += 256) {
        float a = kp_p[i], b = kp_n[i];
        float ra = fmaxf(a, 0.f), rb = fmaxf(b, 0.f);
        g_kp[0][i] = ra;
        g_kp[1][i] = rb;
        lp += 0.1f * fmaxf(1e-6f - a, 0.f) + 0.1f * fmaxf(1e-6f - b, 0.f);
        lp += 0.05f * (ra + rb);
    }
    // gcn neg-penalties on the six 8x8 W's
    if (tid < 64) {
        lp += 0.2f * (fmaxf(1e-6f - Wp1[tid], 0.f) + fmaxf(1e-6f - Wp2[tid], 0.f) +
                      fmaxf(1e-6f - Wp3[tid], 0.f) + fmaxf(1e-6f - Wn1[tid], 0.f) +
                      fmaxf(1e-6f - Wn2[tid], 0.f) + fmaxf(1e-6f - Wn3[tid], 0.f));
    }
    __syncthreads();   // g_kp visible to block

    // gram = kp^T kp, ortho penalty on off-diagonals
    if (tid < 128) {
        int side = tid >> 6, a = (tid >> 3) & 7, b2 = tid & 7;
        const float* kp = g_kp[side];
        float s = 0.f;
        for (int n = 0; n < DIM; n++) s += kp[n * 8 + a] * kp[n * 8 + b2];
        gram_s[tid] = s;
        if (a != b2) lp += 0.2f * s * s;
    }
    __syncthreads();

    // variance of gram diagonal, ddof=1 (0.3 for p-side, 0.5 for n-side)
    if (tid < 2) {
        const float* g = gram_s + tid * 64;
        float mean = 0.f;
        for (int a = 0; a < 8; a++) mean += g[a * 9];
        mean *= 0.125f;
        float v = 0.f;
        for (int a = 0; a < 8; a++) { float d = g[a * 9] - mean; v += d * d; }
        v *= (1.0f / 7.0f);
        lp += (tid ? 0.5f : 0.3f) * v;
    }

    // fused linear:  Wc[c][f] = sum_h lin2_w[c][h] * lin1_w[h][f]
    {
        int c = tid >> 7, f = tid & 127;
        float s = 0.f;
        #pragma unroll
        for (int h = 0; h < 16; h++) s += lin2_w[c * 16 + h] * lin1_w[h * 128 + f];
        g_Wc[tid] = s;
    }
    if (tid < 2) {
        float s = lin2_b[tid];
        #pragma unroll
        for (int h = 0; h < 16; h++) s += lin2_w[tid * 16 + h] * lin1_b[h];
        g_bc[tid] = s;
    }

    atomicAdd(&loss_s, lp);
    __syncthreads();
    if (tid == 0 && write_loss) out[loss_idx] = loss_s;
}

// =====================================================================
// Main: per-batch fused  reduced = kp^T A kp -> 3x GCN -> fused linear
// Double-buffered cp.async staging, kp from constant memory.
// =====================================================================
__global__ void __launch_bounds__(256, 6) gnn_main_kernel(
    const float* __restrict__ A,
    const float* __restrict__ Wp1, const float* __restrict__ Wp2, const float* __restrict__ Wp3,
    const float* __restrict__ Wn1, const float* __restrict__ Wn2, const float* __restrict__ Wn3,
    float* __restrict__ out)
{
    extern __shared__ float sm[];
    float* tile = sm;                    // 2 * TILEF = 8000 floats (double buffer)
    float* W_s  = tile + 2 * TILEF;      // 192 (3 layers x 64)
    float* Rm   = W_s + 192;             // 64
    float* Msm  = Rm + 64;               // 64
    float* Ysm  = Msm + 64;              // 64
    float* Xsm  = Ysm + 64;              // 64
    float* feat = Xsm + 64;              // 128
    float* part = feat + 128;            // 256
    float* AF   = tile;                  // alias: AF (200x8) reuses buffer 0

    const int b = blockIdx.x;
    const int tid = threadIdx.x;

    for (int s = 0; s < 2; s++) {
        // stage the three W's for this sign
        if (tid < 192) {
            const float* w;
            if (s == 0) w = (tid < 64) ? Wp1 : ((tid < 128) ? Wp2 : Wp3);
            else        w = (tid < 64) ? Wn1 : ((tid < 128) ? Wn2 : Wn3);
            W_s[tid] = w[tid & 63];
        }

        const float4* Ag = (const float4*)(A + ((size_t)b * 2 + s) * (DIM * DIM));
        float af[8];
        #pragma unroll
        for (int m = 0; m < 8; m++) af[m] = 0.f;

        // ---- prologue: stage chunk 0 into buffer 0 ----
        {
            float* dstb = tile;
            for (int idx = tid; idx < DIM * (JC / 4); idx += 256) {
                int r  = idx / (JC / 4);
                int c4 = idx - r * (JC / 4);
                cp_async16(dstb + r * TSTRIDE + c4 * 4,
                           Ag + r * (DIM / 4) + c4);
            }
            cp_commit();
        }

        for (int c = 0; c < NCH; c++) {
            // stage next chunk into the other buffer
            if (c + 1 < NCH) {
                float* dstb = tile + ((c + 1) & 1) * TILEF;
                const int j0q = (c + 1) * (JC / 4);
                for (int idx = tid; idx < DIM * (JC / 4); idx += 256) {
                    int r  = idx / (JC / 4);
                    int c4 = idx - r * (JC / 4);
                    cp_async16(dstb + r * TSTRIDE + c4 * 4,
                               Ag + r * (DIM / 4) + j0q + c4);
                }
                cp_commit();
                cp_wait<1>();   // chunk c complete (chunk c+1 may be in flight)
            } else {
                cp_wait<0>();
            }
            __syncthreads();

            // ---- AF[n,:] += adj[n, c*20 : c*20+20] @ kp[c*20 : c*20+20, :] ----
            if (tid < DIM) {
                const float4* t4 = (const float4*)(tile + (c & 1) * TILEF + tid * TSTRIDE);
                const float4* kc = c_kp4[s] + c * JC * 2;
                #pragma unroll
                for (int q = 0; q < JC / 4; q++) {
                    float4 a4 = t4[q];
                    #define GNN_FMA8(aval, jj)                                   \
                        {                                                        \
                            float4 k0 = kc[(4 * q + (jj)) * 2];                  \
                            float4 k1 = kc[(4 * q + (jj)) * 2 + 1];              \
                            af[0] = fmaf((aval), k0.x, af[0]);                   \
                            af[1] = fmaf((aval), k0.y, af[1]);                   \
                            af[2] = fmaf((aval), k0.z, af[2]);                   \
                            af[3] = fmaf((aval), k0.w, af[3]);                   \
                            af[4] = fmaf((aval), k1.x, af[4]);                   \
                            af[5] = fmaf((aval), k1.y, af[5]);                   \
                            af[6] = fmaf((aval), k1.z, af[6]);                   \
                            af[7] = fmaf((aval), k1.w, af[7]);                   \
                        }
                    GNN_FMA8(a4.x, 0)
                    GNN_FMA8(a4.y, 1)
                    GNN_FMA8(a4.z, 2)
                    GNN_FMA8(a4.w, 3)
                    #undef GNN_FMA8
                }
            }
            __syncthreads();    // buffer (c&1) free for reuse at iter c+1
        }

        // ---- write AF to smem (aliases buffer 0; last compute read buffer 1) ----
        if (tid < DIM) {
            #pragma unroll
            for (int m = 0; m < 8; m++) AF[tid * 8 + m] = af[m];
        }
        __syncthreads();

        // ---- fold: reduced[a,m] = sum_n kp[n,a] * AF[n,m] ----
        {
            int g = tid >> 6, am = tid & 63, a = am >> 3, m = am & 7;
            const float* kpf = (const float*)c_kp4[s];
            float sacc = 0.f;
            int n0 = g * 50;
            #pragma unroll 5
            for (int n = n0; n < n0 + 50; n++)
                sacc = fmaf(kpf[n * 8 + a], AF[n * 8 + m], sacc);
            part[tid] = sacc;
        }
        __syncthreads();
        if (tid < 64) Rm[tid] = part[tid] + part[tid + 64] + part[tid + 128] + part[tid + 192];
        __syncthreads();

        // ---- GCN chain on 8x8 (thread (i,j) per element) ----
        const int i = tid >> 3, j = tid & 7;
        for (int l = 0; l < 3; l++) {
            if (tid < 64) {
                float mv;
                if (l == 0) mv = W_s[tid];                   // x=None -> M = W
                else {
                    mv = 0.f;
                    #pragma unroll
                    for (int k = 0; k < 8; k++)
                        mv = fmaf(Xsm[i * 8 + k], W_s[l * 64 + k * 8 + j], mv);
                }
                Msm[tid] = mv;
            }
            __syncthreads();
            if (tid < 64) {
                float t = 0.f;
                #pragma unroll
                for (int k = 0; k < 8; k++)
                    t = fmaf(Rm[i * 8 + k], Msm[k * 8 + j], t);
                float y = ((i == j) ? 1.0f : 0.0f) + 0.85f * t;
                Ysm[tid] = fmaxf(y, 0.f);
            }
            __syncthreads();
            if (tid < 64) {
                float cs = 0.f;
                #pragma unroll
                for (int r = 0; r < 8; r++) cs += Ysm[r * 8 + j];
                float cm = cs * 0.125f + 1e-6f;
                float z = Ysm[tid] / cm;                     // z >= 0
                Xsm[tid] = z + log1pf(__expf(-z));           // softplus, stable
            }
            __syncthreads();
        }
        if (tid < 64) feat[i * 16 + s * 8 + j] = Xsm[tid];   // concat layout (B,8,16)
        __syncthreads();
    }

    // ---- fused 128 -> 2 linear ----
    if (tid < 2) {
        float acc = g_bc[tid];
        const float* w = g_Wc + tid * 128;
        #pragma unroll 8
        for (int f = 0; f < 128; f++) acc = fmaf(w[f], feat[f], acc);
        out[(size_t)b * 2 + tid] = acc;
    }
}

// =====================================================================
extern "C" void kernel_launch(void* const* d_in, const int* in_sizes, int n_in,
                              void* d_out, int out_size)
{
    const float* A        = (const float*)d_in[0];
    const float* kernel_p = (const float*)d_in[1];
    const float* kernel_n = (const float*)d_in[2];
    const float* Wp1      = (const float*)d_in[3];
    const float* Wp2      = (const float*)d_in[4];
    const float* Wp3      = (const float*)d_in[5];
    const float* Wn1      = (const float*)d_in[6];
    const float* Wn2      = (const float*)d_in[7];
    const float* Wn3      = (const float*)d_in[8];
    const float* lin1_w   = (const float*)d_in[9];
    const float* lin1_b   = (const float*)d_in[10];
    const float* lin2_w   = (const float*)d_in[11];
    const float* lin2_b   = (const float*)d_in[12];
    float* out = (float*)d_out;

    const int B = in_sizes[0] / (2 * DIM * DIM);   // 4096
    const int loss_idx = B * 2;
    const int write_loss = (out_size > loss_idx) ? 1 : 0;

    gnn_setup_kernel<<<1, 256>>>(kernel_p, kernel_n, Wp1, Wp2, Wp3, Wn1, Wn2, Wn3,
                                 lin1_w, lin1_b, lin2_w, lin2_b,
                                 out, loss_idx, write_loss);

    // relu'd kernels -> constant memory (async D2D, graph-capturable)
    void* gkp_ptr = nullptr;
    cudaGetSymbolAddress(&gkp_ptr, g_kp);
    cudaMemcpyToSymbolAsync(c_kp4, gkp_ptr, sizeof(float) * 2 * DIM * RED, 0,
                            cudaMemcpyDeviceToDevice, 0);

    const int smem_floats = 2 * TILEF + 192 + 64 + 64 + 64 + 64 + 128 + 256;
    gnn_main_kernel<<<B, 256, smem_floats * sizeof(float)>>>(
        A, Wp1, Wp2, Wp3, Wn1, Wn2, Wn3, out);
}